// round 11
// baseline (speedup 1.0000x reference)
#include <cuda_runtime.h>
#include <cuda_fp16.h>
#include <cstdint>
#include <cstddef>

#define B_ 4
#define H_ 16
#define S_ 2048
#define D_ 64
#define BM 128
#define BN 64
#define NT 256
#define NTILES (S_ / BN)
#define SWORDS (S_ / 32)    // 64 mask words per row

// ---- smem byte offsets ----
#define SM_KHI 0            // [64 d][64 j] f16 (8KB)
#define SM_VHI 8192         // [64 j][64 d] f16 (8KB)
#define SM_QHI 16384        // [128][64] f16 hi (16KB)
#define SM_QLO 32768        // [128][64] f16 lo (16KB)
#define SM_STGK 49152       // f32 staging K tile (16KB)
#define SM_STGV 65536       // f32 staging V tile (16KB)
#define SM_TOTAL 81920      // 80KB -> 2 CTAs/SM = 160KB

#define SWZ1(x) ((x) ^ (((x) >> 3) & 0x70))   // 128B rows
#define LOG2E 1.4426950408889634f

// bit-packed mask scratch: [B][S][S/32] = 2MB
__device__ uint32_t g_mbits[B_ * S_ * SWORDS];

__global__ void pack_mask_kernel(const int* __restrict__ mask) {
  int idx = blockIdx.x * blockDim.x + threadIdx.x;   // over B*S*S
  uint32_t bit = (mask[idx] != 0) ? 1u : 0u;
  uint32_t wv = __ballot_sync(0xffffffffu, bit);
  if ((threadIdx.x & 31) == 0) g_mbits[idx >> 5] = wv;
}

__device__ __forceinline__ uint32_t s2u(const void* p) {
  uint32_t a;
  asm("{ .reg .u64 t; cvta.to.shared.u64 t, %1; cvt.u32.u64 %0, t; }" : "=r"(a) : "l"(p));
  return a;
}
__device__ __forceinline__ void cpasync16(uint32_t saddr, const void* gaddr) {
  asm volatile("cp.async.cg.shared.global [%0], [%1], 16;" :: "r"(saddr), "l"(gaddr));
}
__device__ __forceinline__ void cpasync_commit() {
  asm volatile("cp.async.commit_group;" ::: "memory");
}
__device__ __forceinline__ void cpasync_wait0() {
  asm volatile("cp.async.wait_group 0;" ::: "memory");
}
__device__ __forceinline__ void ldsm4(uint32_t r[4], uint32_t a) {
  asm volatile("ldmatrix.sync.aligned.m8n8.x4.shared.b16 {%0,%1,%2,%3}, [%4];"
               : "=r"(r[0]), "=r"(r[1]), "=r"(r[2]), "=r"(r[3]) : "r"(a));
}
__device__ __forceinline__ void ldsm4t(uint32_t r[4], uint32_t a) {
  asm volatile("ldmatrix.sync.aligned.m8n8.x4.trans.shared.b16 {%0,%1,%2,%3}, [%4];"
               : "=r"(r[0]), "=r"(r[1]), "=r"(r[2]), "=r"(r[3]) : "r"(a));
}
__device__ __forceinline__ void mma16816(float c[4], const uint32_t a[4],
                                         uint32_t b0, uint32_t b1) {
  asm volatile(
    "mma.sync.aligned.m16n8k16.row.col.f32.f16.f16.f32 "
    "{%0,%1,%2,%3}, {%4,%5,%6,%7}, {%8,%9}, {%0,%1,%2,%3};"
    : "+f"(c[0]), "+f"(c[1]), "+f"(c[2]), "+f"(c[3])
    : "r"(a[0]), "r"(a[1]), "r"(a[2]), "r"(a[3]), "r"(b0), "r"(b1));
}
__device__ __forceinline__ uint32_t packh2(float x, float y) {
  __half2 hh = __floats2half2_rn(x, y);
  return *reinterpret_cast<uint32_t*>(&hh);
}
__device__ __forceinline__ float hround(float x) {
  return __half2float(__float2half_rn(x));
}

__global__ void __launch_bounds__(NT, 2)
attn_rf6_kernel(const float* __restrict__ q, const float* __restrict__ k,
                const float* __restrict__ v,
                float* __restrict__ out_o, float* __restrict__ out_s)
{
  extern __shared__ char smc[];
  const uint32_t sb = s2u(smc);

  const int h = blockIdx.x, it = blockIdx.y, b = blockIdx.z;
  const int i0 = it * BM;
  const int bh = b * H_ + h;

  const int tid = threadIdx.x;
  const int lane = tid & 31;
  const int w = tid >> 5;       // 8 warps = 8 row groups of 16; each spans all 64 cols

  const float* qbase = q + ((size_t)bh * S_ + i0) * D_;
  const float* kbase = k + (size_t)bh * D_ * S_;
  const float* vbase = v + (size_t)bh * S_ * D_;

  const int rl0 = w * 16 + (lane >> 2);
  const int rl1 = rl0 + 8;
  const int tq = lane & 3;
  const int sh = tq * 2;
  const int gr0 = i0 + rl0, gr1 = i0 + rl1;
  const uint32_t* mb0 = g_mbits + ((size_t)b * S_ + gr0) * SWORDS;
  const uint32_t* mb1 = g_mbits + ((size_t)b * S_ + gr1) * SWORDS;
  float* srow0 = out_s ? out_s + ((size_t)bh * S_ + gr0) * S_ : nullptr;
  float* srow1 = out_s ? out_s + ((size_t)bh * S_ + gr1) * S_ : nullptr;

  // per-thread cp.async / convert coordinates (4 chunks of 16B each for K and V)
  const int cdd = tid >> 4;            // K: d row 0..15 (x4 via rep), j4 col
  const int cj4 = (tid & 15) * 4;

  // ---- issue cp.async for tile 0 (overlaps with Q processing below) ----
  #pragma unroll
  for (int rep = 0; rep < 4; rep++) {
    int idx = tid + rep * NT;
    int dd = idx >> 4, j4 = (idx & 15) * 4;
    cpasync16(sb + SM_STGK + idx * 16, kbase + (size_t)dd * S_ + j4);
    cpasync16(sb + SM_STGV + idx * 16, vbase + idx * 4);
  }
  cpasync_commit();

  // ---- Q load + fp16 hi/lo split into smem ----
  #pragma unroll
  for (int rep = 0; rep < 8; rep++) {
    int idx = tid + rep * NT;
    int ii = idx >> 4;
    int d4 = (idx & 15) * 4;
    float4 qv = *(const float4*)(qbase + (size_t)ii * D_ + d4);
    float hx = hround(qv.x), hy = hround(qv.y), hz = hround(qv.z), hw = hround(qv.w);
    uint32_t off = SWZ1(ii * 128 + d4 * 2);
    *(uint2*)(smc + SM_QHI + off) = make_uint2(packh2(hx, hy), packh2(hz, hw));
    *(uint2*)(smc + SM_QLO + off) =
        make_uint2(packh2(qv.x - hx, qv.y - hy), packh2(qv.z - hz, qv.w - hw));
  }
  cpasync_wait0();
  __syncthreads();

  // ---- convert tile 0: stage f32 -> f16 planes ----
  #pragma unroll
  for (int rep = 0; rep < 4; rep++) {
    int idx = tid + rep * NT;
    int dd = idx >> 4, j4 = (idx & 15) * 4;
    float4 kv = *(const float4*)(smc + SM_STGK + idx * 16);
    *(uint2*)(smc + SM_KHI + SWZ1(dd * 128 + j4 * 2)) =
        make_uint2(packh2(kv.x, kv.y), packh2(kv.z, kv.w));
    float4 vv = *(const float4*)(smc + SM_STGV + idx * 16);
    *(uint2*)(smc + SM_VHI + SWZ1(dd * 128 + j4 * 2)) =
        make_uint2(packh2(vv.x, vv.y), packh2(vv.z, vv.w));
  }

  // ---- Q fragments persistent in registers ----
  uint32_t qhi[4][4], qlo[4][4];
  #pragma unroll
  for (int ks = 0; ks < 4; ks++) {
    uint32_t ra = SWZ1((w * 16 + (lane & 15)) * 128 + ks * 32 + (lane >> 4) * 16);
    ldsm4(qhi[ks], sb + SM_QHI + ra);
    ldsm4(qlo[ks], sb + SM_QLO + ra);
  }
  __syncthreads();

  float oacc[8][4];
  #pragma unroll
  for (int n = 0; n < 8; n++)
    #pragma unroll
    for (int r = 0; r < 4; r++) oacc[n][r] = 0.f;
  float lsum0 = 0.f, lsum1 = 0.f;

  for (int jt = 0; jt < NTILES; jt++) {
    const int j0 = jt * BN;

    // ---- issue cp.async for tile jt+1 (stage is free; latency covered by compute) ----
    if (jt + 1 < NTILES) {
      const int j0n = j0 + BN;
      #pragma unroll
      for (int rep = 0; rep < 4; rep++) {
        int idx = tid + rep * NT;
        int dd = idx >> 4, j4 = (idx & 15) * 4;
        cpasync16(sb + SM_STGK + idx * 16, kbase + (size_t)dd * S_ + j0n + j4);
        cpasync16(sb + SM_STGV + idx * 16, vbase + (size_t)j0n * D_ + idx * 4);
      }
      cpasync_commit();
    }

    // ---- QK^T: warp computes S[16 x 64]; hi+lo left operand ----
    float sacc[8][4];
    #pragma unroll
    for (int n = 0; n < 8; n++)
      #pragma unroll
      for (int r = 0; r < 4; r++) sacc[n][r] = 0.f;

    #pragma unroll
    for (int ks = 0; ks < 4; ks++) {
      #pragma unroll
      for (int p = 0; p < 4; p++) {
        uint32_t rb = SWZ1((ks * 16 + (lane & 7) + ((lane >> 3) & 1) * 8) * 128 +
                           (p * 16 + (lane >> 4) * 8) * 2);
        uint32_t bhi[4];
        ldsm4t(bhi, sb + SM_KHI + rb);
        mma16816(sacc[2*p],   qhi[ks], bhi[0], bhi[1]);
        mma16816(sacc[2*p+1], qhi[ks], bhi[2], bhi[3]);
        mma16816(sacc[2*p],   qlo[ks], bhi[0], bhi[1]);
        mma16816(sacc[2*p+1], qlo[ks], bhi[2], bhi[3]);
      }
    }

    // ---- epilogue: bitmask, scale, score STG, exp, hi/lo split of P ----
    const uint2 mw0 = *(const uint2*)(mb0 + jt * 2);
    const uint2 mw1 = *(const uint2*)(mb1 + jt * 2);
    uint32_t PH[8][2], PL[8][2];
    #pragma unroll
    for (int n = 0; n < 8; n++) {
      uint32_t bb0 = ((n < 4) ? mw0.x : mw0.y) >> ((n & 3) * 8 + sh);
      uint32_t bb1 = ((n < 4) ? mw1.x : mw1.y) >> ((n & 3) * 8 + sh);
      float s0 = (bb0 & 1u) ? sacc[n][0] * 0.125f : -1e10f;
      float s1 = (bb0 & 2u) ? sacc[n][1] * 0.125f : -1e10f;
      float s2 = (bb1 & 1u) ? sacc[n][2] * 0.125f : -1e10f;
      float s3 = (bb1 & 2u) ? sacc[n][3] * 0.125f : -1e10f;
      int gc = j0 + n * 8 + sh;
      if (srow0) {
        *(float2*)(srow0 + gc) = make_float2(s0, s1);
        *(float2*)(srow1 + gc) = make_float2(s2, s3);
      }
      float p0 = exp2f(s0 * LOG2E);
      float p1 = exp2f(s1 * LOG2E);
      float p2 = exp2f(s2 * LOG2E);
      float p3 = exp2f(s3 * LOG2E);
      lsum0 += p0 + p1;
      lsum1 += p2 + p3;
      float h0 = hround(p0), h1 = hround(p1), h2 = hround(p2), h3 = hround(p3);
      PH[n][0] = packh2(h0, h1);
      PH[n][1] = packh2(h2, h3);
      PL[n][0] = packh2(p0 - h0, p1 - h1);
      PL[n][1] = packh2(p2 - h2, p3 - h3);
    }

    // ---- PV: A = P hi/lo fragments (regs), B = V hi ----
    #pragma unroll
    for (int kc = 0; kc < 4; kc++) {
      uint32_t ah[4] = {PH[2*kc][0], PH[2*kc][1], PH[2*kc+1][0], PH[2*kc+1][1]};
      uint32_t al[4] = {PL[2*kc][0], PL[2*kc][1], PL[2*kc+1][0], PL[2*kc+1][1]};
      #pragma unroll
      for (int pb = 0; pb < 4; pb++) {
        uint32_t rb = SWZ1((kc * 16 + (lane & 7) + ((lane >> 3) & 1) * 8) * 128 +
                           (pb * 16 + (lane >> 4) * 8) * 2);
        uint32_t vh[4];
        ldsm4t(vh, sb + SM_VHI + rb);
        mma16816(oacc[2*pb],   ah, vh[0], vh[1]);
        mma16816(oacc[2*pb+1], ah, vh[2], vh[3]);
        mma16816(oacc[2*pb],   al, vh[0], vh[1]);
        mma16816(oacc[2*pb+1], al, vh[2], vh[3]);
      }
    }

    // ---- pipeline tail: stage data arrived; convert into f16 planes ----
    if (jt + 1 < NTILES) {
      cpasync_wait0();
      __syncthreads();   // all warps done reading f16 planes; stage complete everywhere
      #pragma unroll
      for (int rep = 0; rep < 4; rep++) {
        int idx = tid + rep * NT;
        int dd = idx >> 4, j4 = (idx & 15) * 4;
        float4 kv = *(const float4*)(smc + SM_STGK + idx * 16);
        *(uint2*)(smc + SM_KHI + SWZ1(dd * 128 + j4 * 2)) =
            make_uint2(packh2(kv.x, kv.y), packh2(kv.z, kv.w));
        float4 vv = *(const float4*)(smc + SM_STGV + idx * 16);
        *(uint2*)(smc + SM_VHI + SWZ1(dd * 128 + j4 * 2)) =
            make_uint2(packh2(vv.x, vv.y), packh2(vv.z, vv.w));
      }
      __syncthreads();   // f16 planes ready for next tile
    }
  }

  // ---- finalize: quad-local l reduction ----
  lsum0 += __shfl_xor_sync(0xffffffffu, lsum0, 1);
  lsum0 += __shfl_xor_sync(0xffffffffu, lsum0, 2);
  lsum1 += __shfl_xor_sync(0xffffffffu, lsum1, 1);
  lsum1 += __shfl_xor_sync(0xffffffffu, lsum1, 2);
  if (out_o) {
    float inv0 = 1.0f / lsum0, inv1 = 1.0f / lsum1;
    float* orow0 = out_o + ((size_t)bh * S_ + gr0) * D_;
    float* orow1 = out_o + ((size_t)bh * S_ + gr1) * D_;
    #pragma unroll
    for (int n = 0; n < 8; n++) {
      int cl = n * 8 + sh;
      *(float2*)(orow0 + cl) = make_float2(oacc[n][0] * inv0, oacc[n][1] * inv0);
      *(float2*)(orow1 + cl) = make_float2(oacc[n][2] * inv1, oacc[n][3] * inv1);
    }
  }
  (void)cdd; (void)cj4;
}

extern "C" void kernel_launch(void* const* d_in, const int* in_sizes, int n_in,
                              void* d_out, int out_size) {
  const float* q = (const float*)d_in[0];
  const float* k = (const float*)d_in[1];
  const float* v = (const float*)d_in[2];
  const int* mask = (const int*)d_in[3];

  const size_t nO = (size_t)B_ * H_ * S_ * D_;   // 8388608
  const size_t nS = (size_t)B_ * H_ * S_ * S_;   // 268435456

  float* base = (float*)d_out;
  float* out_o = nullptr;
  float* out_s = nullptr;
  if ((size_t)out_size == nO + nS) { out_o = base; out_s = base + nO; }
  else if ((size_t)out_size == nS) { out_s = base; }
  else                             { out_o = base; }

  // 1) bit-pack the mask
  pack_mask_kernel<<<(B_ * S_ * S_) / 256, 256>>>(mask);

  // 2) fused attention
  cudaFuncSetAttribute(attn_rf6_kernel,
                       cudaFuncAttributeMaxDynamicSharedMemorySize, SM_TOTAL);
  dim3 grid(H_, S_ / BM, B_);   // (16, 16, 4) — h fastest for K/V + mask L2 reuse
  attn_rf6_kernel<<<grid, NT, SM_TOTAL>>>(q, k, v, out_o, out_s);
}

// round 12
// speedup vs baseline: 1.1155x; 1.1155x over previous
#include <cuda_runtime.h>
#include <cuda_fp16.h>
#include <cstdint>
#include <cstddef>

#define B_ 4
#define H_ 16
#define S_ 2048
#define D_ 64
#define BM 128
#define BN 64
#define NT 256
#define NTILES (S_ / BN)
#define SWORDS (S_ / 32)    // 64 mask words per row

// ---- smem byte offsets ----
#define SM_KHI 0            // [64 d][64 j] f16 (8KB)
#define SM_VHI 8192         // [64 j][64 d] f16 (8KB)
#define SM_QHI 16384        // [128][64] f16 (16KB)
#define SM_TOTAL 32768

#define SWZ1(x) ((x) ^ (((x) >> 3) & 0x70))   // 128B rows
#define LOG2E 1.4426950408889634f

// bit-packed mask scratch: [B][S][S/32] = 2MB
__device__ uint32_t g_mbits[B_ * S_ * SWORDS];

__global__ void pack_mask_kernel(const int* __restrict__ mask) {
  int idx = blockIdx.x * blockDim.x + threadIdx.x;   // over B*S*S
  uint32_t bit = (mask[idx] != 0) ? 1u : 0u;
  uint32_t wv = __ballot_sync(0xffffffffu, bit);
  if ((threadIdx.x & 31) == 0) g_mbits[idx >> 5] = wv;
}

__device__ __forceinline__ uint32_t s2u(const void* p) {
  uint32_t a;
  asm("{ .reg .u64 t; cvta.to.shared.u64 t, %1; cvt.u32.u64 %0, t; }" : "=r"(a) : "l"(p));
  return a;
}
__device__ __forceinline__ void ldsm4(uint32_t r[4], uint32_t a) {
  asm volatile("ldmatrix.sync.aligned.m8n8.x4.shared.b16 {%0,%1,%2,%3}, [%4];"
               : "=r"(r[0]), "=r"(r[1]), "=r"(r[2]), "=r"(r[3]) : "r"(a));
}
__device__ __forceinline__ void ldsm4t(uint32_t r[4], uint32_t a) {
  asm volatile("ldmatrix.sync.aligned.m8n8.x4.trans.shared.b16 {%0,%1,%2,%3}, [%4];"
               : "=r"(r[0]), "=r"(r[1]), "=r"(r[2]), "=r"(r[3]) : "r"(a));
}
__device__ __forceinline__ void mma16816(float c[4], const uint32_t a[4],
                                         uint32_t b0, uint32_t b1) {
  asm volatile(
    "mma.sync.aligned.m16n8k16.row.col.f32.f16.f16.f32 "
    "{%0,%1,%2,%3}, {%4,%5,%6,%7}, {%8,%9}, {%0,%1,%2,%3};"
    : "+f"(c[0]), "+f"(c[1]), "+f"(c[2]), "+f"(c[3])
    : "r"(a[0]), "r"(a[1]), "r"(a[2]), "r"(a[3]), "r"(b0), "r"(b1));
}
__device__ __forceinline__ uint32_t packh2(float x, float y) {
  __half2 hh = __floats2half2_rn(x, y);
  return *reinterpret_cast<uint32_t*>(&hh);
}
__device__ __forceinline__ float hround(float x) {
  return __half2float(__float2half_rn(x));
}

__global__ void __launch_bounds__(NT, 2)
attn_rf7_kernel(const float* __restrict__ q, const float* __restrict__ k,
                const float* __restrict__ v,
                float* __restrict__ out_o, float* __restrict__ out_s)
{
  extern __shared__ char smc[];
  const uint32_t sb = s2u(smc);

  const int h = blockIdx.x, it = blockIdx.y, b = blockIdx.z;
  const int i0 = it * BM;
  const int bh = b * H_ + h;

  const int tid = threadIdx.x;
  const int lane = tid & 31;
  const int w = tid >> 5;       // 8 warps = 8 row groups of 16; each spans all 64 cols

  const float* qbase = q + ((size_t)bh * S_ + i0) * D_;
  const float* kbase = k + (size_t)bh * D_ * S_;
  const float* vbase = v + (size_t)bh * S_ * D_;

  const int rl0 = w * 16 + (lane >> 2);
  const int rl1 = rl0 + 8;
  const int tq = lane & 3;
  const int sh = tq * 2;
  const int gr0 = i0 + rl0, gr1 = i0 + rl1;
  const uint32_t* mb0 = g_mbits + ((size_t)b * S_ + gr0) * SWORDS;
  const uint32_t* mb1 = g_mbits + ((size_t)b * S_ + gr1) * SWORDS;
  float* srow0 = out_s ? out_s + ((size_t)bh * S_ + gr0) * S_ : nullptr;
  float* srow1 = out_s ? out_s + ((size_t)bh * S_ + gr1) * S_ : nullptr;

  // ---- Q load -> fp16 (single plane) into smem ----
  #pragma unroll
  for (int rep = 0; rep < 8; rep++) {
    int idx = tid + rep * NT;
    int ii = idx >> 4;
    int d4 = (idx & 15) * 4;
    float4 qv = *(const float4*)(qbase + (size_t)ii * D_ + d4);
    uint32_t off = SWZ1(ii * 128 + d4 * 2);
    *(uint2*)(smc + SM_QHI + off) =
        make_uint2(packh2(qv.x, qv.y), packh2(qv.z, qv.w));
  }
  __syncthreads();

  // ---- Q fragments persistent in registers (rows w*16..w*16+16) ----
  uint32_t qhi[4][4];
  #pragma unroll
  for (int ks = 0; ks < 4; ks++) {
    uint32_t ra = SWZ1((w * 16 + (lane & 15)) * 128 + ks * 32 + (lane >> 4) * 16);
    ldsm4(qhi[ks], sb + SM_QHI + ra);
  }

  float oacc[8][4];
  #pragma unroll
  for (int n = 0; n < 8; n++)
    #pragma unroll
    for (int r = 0; r < 4; r++) oacc[n][r] = 0.f;
  float lsum0 = 0.f, lsum1 = 0.f;

  for (int jt = 0; jt < NTILES; jt++) {
    const int j0 = jt * BN;

    __syncthreads();   // prior tile's smem readers done
    // ---- K tile: [64 d][64 j] LDG -> rn16 -> STS ----
    #pragma unroll
    for (int rep = 0; rep < 4; rep++) {
      int idx = tid + rep * NT;
      int dd = idx >> 4, j4 = (idx & 15) * 4;
      float4 kv = *(const float4*)(kbase + (size_t)dd * S_ + j0 + j4);
      uint32_t off = SWZ1(dd * 128 + j4 * 2);
      *(uint2*)(smc + SM_KHI + off) =
          make_uint2(packh2(kv.x, kv.y), packh2(kv.z, kv.w));
    }
    // ---- V tile: [64 j][64 d] ----
    #pragma unroll
    for (int rep = 0; rep < 4; rep++) {
      int idx = tid + rep * NT;
      float4 vv = *(const float4*)(vbase + (size_t)j0 * D_ + idx * 4);
      int jj = idx >> 4, d4 = (idx & 15) * 4;
      uint32_t off = SWZ1(jj * 128 + d4 * 2);
      *(uint2*)(smc + SM_VHI + off) =
          make_uint2(packh2(vv.x, vv.y), packh2(vv.z, vv.w));
    }
    __syncthreads();

    // ---- QK^T: warp computes S[16 x 64]; single fp16 pass ----
    float sacc[8][4];
    #pragma unroll
    for (int n = 0; n < 8; n++)
      #pragma unroll
      for (int r = 0; r < 4; r++) sacc[n][r] = 0.f;

    #pragma unroll
    for (int ks = 0; ks < 4; ks++) {
      #pragma unroll
      for (int p = 0; p < 4; p++) {
        uint32_t rb = SWZ1((ks * 16 + (lane & 7) + ((lane >> 3) & 1) * 8) * 128 +
                           (p * 16 + (lane >> 4) * 8) * 2);
        uint32_t bhi[4];
        ldsm4t(bhi, sb + SM_KHI + rb);
        mma16816(sacc[2*p],   qhi[ks], bhi[0], bhi[1]);
        mma16816(sacc[2*p+1], qhi[ks], bhi[2], bhi[3]);
      }
    }

    // ---- epilogue: bitmask, scale, score STG, exp, hi/lo split of P ----
    const uint2 mw0 = *(const uint2*)(mb0 + jt * 2);
    const uint2 mw1 = *(const uint2*)(mb1 + jt * 2);
    uint32_t PH[8][2], PL[8][2];
    #pragma unroll
    for (int n = 0; n < 8; n++) {
      uint32_t bb0 = ((n < 4) ? mw0.x : mw0.y) >> ((n & 3) * 8 + sh);
      uint32_t bb1 = ((n < 4) ? mw1.x : mw1.y) >> ((n & 3) * 8 + sh);
      float s0 = (bb0 & 1u) ? sacc[n][0] * 0.125f : -1e10f;
      float s1 = (bb0 & 2u) ? sacc[n][1] * 0.125f : -1e10f;
      float s2 = (bb1 & 1u) ? sacc[n][2] * 0.125f : -1e10f;
      float s3 = (bb1 & 2u) ? sacc[n][3] * 0.125f : -1e10f;
      int gc = j0 + n * 8 + sh;
      if (srow0) {
        *(float2*)(srow0 + gc) = make_float2(s0, s1);
        *(float2*)(srow1 + gc) = make_float2(s2, s3);
      }
      float p0 = exp2f(s0 * LOG2E);
      float p1 = exp2f(s1 * LOG2E);
      float p2 = exp2f(s2 * LOG2E);
      float p3 = exp2f(s3 * LOG2E);
      lsum0 += p0 + p1;
      lsum1 += p2 + p3;
      float h0 = hround(p0), h1 = hround(p1), h2 = hround(p2), h3 = hround(p3);
      PH[n][0] = packh2(h0, h1);
      PH[n][1] = packh2(h2, h3);
      PL[n][0] = packh2(p0 - h0, p1 - h1);
      PL[n][1] = packh2(p2 - h2, p3 - h3);
    }

    // ---- PV: A = P hi/lo fragments (regs), B = V fp16 ----
    #pragma unroll
    for (int kc = 0; kc < 4; kc++) {
      uint32_t ah[4] = {PH[2*kc][0], PH[2*kc][1], PH[2*kc+1][0], PH[2*kc+1][1]};
      uint32_t al[4] = {PL[2*kc][0], PL[2*kc][1], PL[2*kc+1][0], PL[2*kc+1][1]};
      #pragma unroll
      for (int pb = 0; pb < 4; pb++) {
        uint32_t rb = SWZ1((kc * 16 + (lane & 7) + ((lane >> 3) & 1) * 8) * 128 +
                           (pb * 16 + (lane >> 4) * 8) * 2);
        uint32_t vh[4];
        ldsm4t(vh, sb + SM_VHI + rb);
        mma16816(oacc[2*pb],   ah, vh[0], vh[1]);
        mma16816(oacc[2*pb+1], ah, vh[2], vh[3]);
        mma16816(oacc[2*pb],   al, vh[0], vh[1]);
        mma16816(oacc[2*pb+1], al, vh[2], vh[3]);
      }
    }
  }

  // ---- finalize: quad-local l reduction ----
  lsum0 += __shfl_xor_sync(0xffffffffu, lsum0, 1);
  lsum0 += __shfl_xor_sync(0xffffffffu, lsum0, 2);
  lsum1 += __shfl_xor_sync(0xffffffffu, lsum1, 1);
  lsum1 += __shfl_xor_sync(0xffffffffu, lsum1, 2);
  if (out_o) {
    float inv0 = 1.0f / lsum0, inv1 = 1.0f / lsum1;
    float* orow0 = out_o + ((size_t)bh * S_ + gr0) * D_;
    float* orow1 = out_o + ((size_t)bh * S_ + gr1) * D_;
    #pragma unroll
    for (int n = 0; n < 8; n++) {
      int cl = n * 8 + sh;
      *(float2*)(orow0 + cl) = make_float2(oacc[n][0] * inv0, oacc[n][1] * inv0);
      *(float2*)(orow1 + cl) = make_float2(oacc[n][2] * inv1, oacc[n][3] * inv1);
    }
  }
}

extern "C" void kernel_launch(void* const* d_in, const int* in_sizes, int n_in,
                              void* d_out, int out_size) {
  const float* q = (const float*)d_in[0];
  const float* k = (const float*)d_in[1];
  const float* v = (const float*)d_in[2];
  const int* mask = (const int*)d_in[3];

  const size_t nO = (size_t)B_ * H_ * S_ * D_;   // 8388608
  const size_t nS = (size_t)B_ * H_ * S_ * S_;   // 268435456

  float* base = (float*)d_out;
  float* out_o = nullptr;
  float* out_s = nullptr;
  if ((size_t)out_size == nO + nS) { out_o = base; out_s = base + nO; }
  else if ((size_t)out_size == nS) { out_s = base; }
  else                             { out_o = base; }

  // 1) bit-pack the mask
  pack_mask_kernel<<<(B_ * S_ * S_) / 256, 256>>>(mask);

  // 2) fused attention
  cudaFuncSetAttribute(attn_rf7_kernel,
                       cudaFuncAttributeMaxDynamicSharedMemorySize, SM_TOTAL);
  dim3 grid(H_, S_ / BM, B_);   // (16, 16, 4) — h fastest for K/V + mask L2 reuse
  attn_rf7_kernel<<<grid, NT, SM_TOTAL>>>(q, k, v, out_o, out_s);
}